// round 4
// baseline (speedup 1.0000x reference)
#include <cuda_runtime.h>
#include <cuda_bf16.h>
#include <cstdint>

#define B_   128
#define S_   512
#define D_   2048
#define N_   128
#define NN_  16384
#define KT   32
#define PAD  40      /* fp32 words per smem row: 160B -> conflict-free frag loads */
#define STAGES 3

// ---------------- scratch (device globals; no allocation) ----------------
__device__ __align__(16) float g_mean[B_ * D_];      // 1 MB
__device__ __align__(16) float g_ctx [B_ * D_];      // 1 MB
__device__ __align__(16) float g_warp[B_ * NN_];     // 8 MB
__device__ __align__(16) float g_part[128 * NN_];    // 8 MB split-K partials for raw

// ---------------- helpers ----------------
__device__ __forceinline__ void cp_async16(void* smem, const void* gmem) {
    uint32_t s = (uint32_t)__cvta_generic_to_shared(smem);
    asm volatile("cp.async.cg.shared.global [%0], [%1], 16;\n" :: "r"(s), "l"(gmem));
}
__device__ __forceinline__ uint32_t f2bf2(float lo, float hi) {
    uint32_t r;
    asm("cvt.rn.bf16x2.f32 %0, %1, %2;" : "=r"(r) : "f"(hi), "f"(lo));  // hi -> upper 16
    return r;
}
__device__ __forceinline__ void mma_bf16(float* c, const uint32_t* a, const uint32_t* b) {
    asm volatile(
        "mma.sync.aligned.m16n8k16.row.col.f32.bf16.bf16.f32 "
        "{%0,%1,%2,%3}, {%4,%5,%6,%7}, {%8,%9}, {%0,%1,%2,%3};"
        : "+f"(c[0]), "+f"(c[1]), "+f"(c[2]), "+f"(c[3])
        : "r"(a[0]), "r"(a[1]), "r"(a[2]), "r"(a[3]), "r"(b[0]), "r"(b[1]));
}

// ---------------- kernel 1: mean over sequence ----------------
__global__ void k_mean(const float4* __restrict__ x4, float4* __restrict__ m4) {
    int b  = blockIdx.x >> 3;
    int d4 = ((blockIdx.x & 7) << 6) + threadIdx.x;     // 0..511
    const float4* p = x4 + (size_t)b * (S_ * D_ / 4) + d4;
    float4 acc[8];
    #pragma unroll
    for (int u = 0; u < 8; u++) acc[u] = make_float4(0.f, 0.f, 0.f, 0.f);
    for (int s = 0; s < S_; s += 8) {
        #pragma unroll
        for (int u = 0; u < 8; u++) {
            float4 v = __ldcs(&p[(size_t)(s + u) * (D_ / 4)]);
            acc[u].x += v.x; acc[u].y += v.y; acc[u].z += v.z; acc[u].w += v.w;
        }
    }
    #pragma unroll
    for (int u = 0; u < 4; u++) {
        acc[u].x += acc[u+4].x; acc[u].y += acc[u+4].y;
        acc[u].z += acc[u+4].z; acc[u].w += acc[u+4].w;
    }
    acc[0].x += acc[2].x; acc[0].y += acc[2].y; acc[0].z += acc[2].z; acc[0].w += acc[2].w;
    acc[1].x += acc[3].x; acc[1].y += acc[3].y; acc[1].z += acc[3].z; acc[1].w += acc[3].w;
    const float inv = 1.f / (float)S_;
    float4 m;
    m.x = (acc[0].x + acc[1].x) * inv;
    m.y = (acc[0].y + acc[1].y) * inv;
    m.z = (acc[0].z + acc[1].z) * inv;
    m.w = (acc[0].w + acc[1].w) * inv;
    m4[b * (D_ / 4) + d4] = m;
}

// ---------------- cp.async 3-stage GEMM, 512 threads (16 warps, 4x4) ----------------
// out[128, Nfull] = A[128,2048] @ Bm[Nfull,2048]^T, NT cols per block.
// EPI: 1 = +bias, 2 = (+bias)*0.1
// warp (wy,wx): rows [32*wy, +32), cols [wx*NT/4, +NT/4).
template<int NT, int EPI>
__global__ void __launch_bounds__(512, 1)
k_gemm(const float* __restrict__ A, const float* __restrict__ Bm,
       const float* __restrict__ bias, float* __restrict__ out, int Nfull) {
    constexpr int ASZ = 128 * PAD;
    constexpr int BSZ = NT  * PAD;
    constexpr int NJ  = NT / 32;             // n8 tiles per warp (NT/4 cols / 8)
    constexpr int NA4 = 128 * (KT/4) / 512;  // A float4 ops per thread = 2
    constexpr int NB4 = (NT * (KT/4) + 511) / 512;

    extern __shared__ __align__(16) float sm[];
    float* As = sm;                          // [STAGES][128][PAD]
    float* Bs = sm + STAGES * ASZ;           // [STAGES][NT ][PAD]

    const int tid  = threadIdx.x;
    const int warp = tid >> 5, lane = tid & 31;
    const int wy   = warp >> 2, wx = warp & 3;
    const int row0 = wy * 32;
    const int n0   = blockIdx.x * NT;
    const int wxn0 = wx * (NT / 4);
    const int r    = lane >> 2, c = lane & 3;

    float acc[2][NJ][4];
    #pragma unroll
    for (int m = 0; m < 2; m++)
        #pragma unroll
        for (int j = 0; j < NJ; j++)
            acc[m][j][0] = acc[m][j][1] = acc[m][j][2] = acc[m][j][3] = 0.f;

    auto issue = [&](int kt) {
        int st = kt % STAGES;
        int k0 = kt * KT;
        #pragma unroll
        for (int u = 0; u < NA4; u++) {                     // A: 128x32 fp32
            int i  = tid + u * 512;
            int rr = i >> 3, cc = (i & 7) * 4;
            cp_async16(&As[st * ASZ + rr * PAD + cc], &A[(size_t)rr * D_ + k0 + cc]);
        }
        #pragma unroll
        for (int u = 0; u < NB4; u++) {                     // B: NTx32 fp32
            int i  = tid + u * 512;
            if (NT * (KT/4) % 512 == 0 || i < NT * (KT/4)) {
                int rr = i >> 3, cc = (i & 7) * 4;
                cp_async16(&Bs[st * BSZ + rr * PAD + cc], &Bm[(size_t)(n0 + rr) * D_ + k0 + cc]);
            }
        }
        asm volatile("cp.async.commit_group;\n");
    };

    constexpr int NK = D_ / KT;   // 64
    #pragma unroll
    for (int s = 0; s < STAGES - 1; s++) issue(s);

    for (int kt = 0; kt < NK; kt++) {
        int st = kt % STAGES;
        asm volatile("cp.async.wait_group %0;\n" :: "n"(STAGES - 2));
        __syncthreads();
        if (kt + STAGES - 1 < NK) issue(kt + STAGES - 1);

        const float* Ast = As + st * ASZ;
        const float* Bst = Bs + st * BSZ;
        #pragma unroll
        for (int h = 0; h < 2; h++) {
            const int kb = h * 16 + 2 * c;
            uint32_t a[2][4];
            #pragma unroll
            for (int m = 0; m < 2; m++) {
                const float* ap = Ast + (row0 + m * 16 + r) * PAD + kb;
                float2 v;
                v = *(const float2*)(ap);                 a[m][0] = f2bf2(v.x, v.y);
                v = *(const float2*)(ap + 8 * PAD);       a[m][1] = f2bf2(v.x, v.y);
                v = *(const float2*)(ap + 8);             a[m][2] = f2bf2(v.x, v.y);
                v = *(const float2*)(ap + 8 * PAD + 8);   a[m][3] = f2bf2(v.x, v.y);
            }
            #pragma unroll
            for (int j = 0; j < NJ; j++) {
                const float* bp = Bst + (wxn0 + j * 8 + r) * PAD + kb;
                float2 v;
                uint32_t b[2];
                v = *(const float2*)(bp);       b[0] = f2bf2(v.x, v.y);
                v = *(const float2*)(bp + 8);   b[1] = f2bf2(v.x, v.y);
                mma_bf16(acc[0][j], a[0], b);
                mma_bf16(acc[1][j], a[1], b);
            }
        }
        __syncthreads();
    }

    #pragma unroll
    for (int m = 0; m < 2; m++) {
        #pragma unroll
        for (int j = 0; j < NJ; j++) {
            int row = row0 + m * 16 + r;
            int col = n0 + wxn0 + j * 8 + 2 * c;
            float bv0 = bias[col], bv1 = bias[col + 1];
            float o00 = acc[m][j][0] + bv0, o01 = acc[m][j][1] + bv1;
            float o10 = acc[m][j][2] + bv0, o11 = acc[m][j][3] + bv1;
            if (EPI == 2) { o00 *= 0.1f; o01 *= 0.1f; o10 *= 0.1f; o11 *= 0.1f; }
            out[(size_t)row       * Nfull + col    ] = o00;
            out[(size_t)row       * Nfull + col + 1] = o01;
            out[(size_t)(row + 8) * Nfull + col    ] = o10;
            out[(size_t)(row + 8) * Nfull + col + 1] = o11;
        }
    }
}

// ---------------- raw-score split-K partials (fp32, deterministic) ----------------
__global__ void k_rawpart(const float* __restrict__ ctx, const float* __restrict__ rs,
                          float* __restrict__ part) {
    __shared__ float cs [128][20];
    __shared__ float rss[128][20];
    const int tid = threadIdx.x;
    const int k0  = blockIdx.x * 16;
    #pragma unroll
    for (int u = 0; u < 2; u++) {
        int i  = tid + u * 256;
        int rr = i >> 2, cc = (i & 3) * 4;
        *(float4*)&cs [rr][cc] = *(const float4*)&ctx[(size_t)rr * D_ + k0 + cc];
        *(float4*)&rss[rr][cc] = *(const float4*)&rs [(size_t)rr * D_ + k0 + cc];
    }
    __syncthreads();
    const int bb = tid >> 4;
    const int jj = tid & 15;
    float a[8][8];
    #pragma unroll
    for (int u = 0; u < 8; u++)
        #pragma unroll
        for (int v = 0; v < 8; v++) a[u][v] = 0.f;
    #pragma unroll
    for (int k = 0; k < 16; k++) {
        float cv[8], rv[8];
        #pragma unroll
        for (int u = 0; u < 8; u++) { cv[u] = cs[bb + 16*u][k]; rv[u] = rss[jj + 16*u][k]; }
        #pragma unroll
        for (int u = 0; u < 8; u++)
            #pragma unroll
            for (int v = 0; v < 8; v++) a[u][v] += cv[u] * rv[v];
    }
    float* po = part + (size_t)blockIdx.x * NN_;
    #pragma unroll
    for (int u = 0; u < 8; u++)
        #pragma unroll
        for (int v = 0; v < 8; v++)
            po[(bb + 16*u) * N_ + (jj + 16*v)] = a[u][v];
}

// ---------------- final: reduce raw partials + softmax + warped scores + sigmoid ----------------
__global__ void k_final(const float* __restrict__ adj, const float* __restrict__ warp_,
                        const float* __restrict__ part, float* __restrict__ out) {
    extern __shared__ float smf[];
    float (*s)[129] = reinterpret_cast<float(*)[129]>(smf);
    float* raws = smf + 128 * 129;
    const int b = blockIdx.x, t = threadIdx.x;

    float rsum = 0.f;
    #pragma unroll 8
    for (int ks = 0; ks < 128; ks++) rsum += part[(size_t)ks * NN_ + b * N_ + t];
    raws[t] = rsum;

    const float* wp = warp_ + (size_t)b * NN_;
    for (int idx = t; idx < NN_; idx += 128)
        s[idx >> 7][idx & 127] = adj[idx] + wp[idx];
    __syncthreads();

    float m = -1e30f;
    #pragma unroll 4
    for (int j = 0; j < N_; j++) m = fmaxf(m, s[t][j]);
    float sum = 0.f, dot = 0.f;
    #pragma unroll 4
    for (int j = 0; j < N_; j++) {
        float e = __expf(s[t][j] - m);
        sum += e;
        dot += e * raws[j];
    }
    float w = dot / sum;
    out[b * N_ + t] = 1.f / (1.f + __expf(-w));
}

// ---------------- launch ----------------
extern "C" void kernel_launch(void* const* d_in, const int* in_sizes, int n_in,
                              void* d_out, int out_size) {
    const float* x   = (const float*)d_in[0];
    const float* rs  = (const float*)d_in[1];
    const float* Wc  = (const float*)d_in[2];
    const float* bc  = (const float*)d_in[3];
    const float* Ww  = (const float*)d_in[4];
    const float* bw  = (const float*)d_in[5];
    const float* adj = (const float*)d_in[6];
    float* out = (float*)d_out;

    float *p_mean, *p_ctx, *p_warp, *p_part;
    cudaGetSymbolAddress((void**)&p_mean, g_mean);
    cudaGetSymbolAddress((void**)&p_ctx,  g_ctx);
    cudaGetSymbolAddress((void**)&p_warp, g_warp);
    cudaGetSymbolAddress((void**)&p_part, g_part);

    // 1. mean over S  (HBM-bound, 512 MB)
    k_mean<<<B_ * 8, 64>>>((const float4*)x, (float4*)p_mean);

    // 2. context = mean @ Wc^T + bc
    {
        size_t sh = (size_t)(STAGES * 128 * PAD + STAGES * 32 * PAD) * sizeof(float);
        cudaFuncSetAttribute(k_gemm<32, 1>, cudaFuncAttributeMaxDynamicSharedMemorySize, (int)sh);
        k_gemm<32, 1><<<D_ / 32, 512, sh>>>(p_mean, Wc, bc, p_ctx, D_);
    }

    // 3. raw partials = ctx @ rs^T
    k_rawpart<<<128, 256>>>(p_ctx, rs, p_part);

    // 4. warp = 0.1*(ctx @ Ww^T + bw)
    {
        size_t sh = (size_t)(STAGES * 128 * PAD + STAGES * 128 * PAD) * sizeof(float);
        cudaFuncSetAttribute(k_gemm<128, 2>, cudaFuncAttributeMaxDynamicSharedMemorySize, (int)sh);
        k_gemm<128, 2><<<NN_ / 128, 512, sh>>>(p_ctx, Ww, bw, p_warp, NN_);
    }

    // 5. reduce raw + softmax(adj + warp) @ raw -> sigmoid
    {
        size_t sh = (size_t)(128 * 129 + 128) * sizeof(float);
        cudaFuncSetAttribute(k_final, cudaFuncAttributeMaxDynamicSharedMemorySize, (int)sh);
        k_final<<<B_, 128, sh>>>(adj, p_warp, p_part, out);
    }
}

// round 6
// speedup vs baseline: 1.2585x; 1.2585x over previous
#include <cuda_runtime.h>
#include <cuda_bf16.h>
#include <cstdint>

#define B_    128
#define S_    512
#define D_    2048
#define N_    128
#define NN_   16384
#define KTILE 64
#define PADG  72     /* fp32 words per smem row (64 + 8): conflict-free LDS.64 */
#define STG   3

// ---------------- scratch (device globals; no allocation) ----------------
__device__ __align__(16) float g_mean[B_ * D_];        // 1 MB
__device__ __align__(16) float g_ctx [B_ * D_];        // 1 MB
__device__ __align__(16) float g_ctxp[2 * B_ * D_];    // 2 MB gemm1 split-K partials
__device__ __align__(16) float g_part[128 * NN_];      // 8 MB raw split-K partials
__device__ __align__(16) float g_raw [NN_];            // 64 KB

// ---------------- helpers ----------------
__device__ __forceinline__ void cp_async16(void* smem, const void* gmem) {
    uint32_t s = (uint32_t)__cvta_generic_to_shared(smem);
    asm volatile("cp.async.cg.shared.global [%0], [%1], 16;\n" :: "r"(s), "l"(gmem));
}
__device__ __forceinline__ uint32_t f2bf2(float lo, float hi) {
    uint32_t r;
    asm("cvt.rn.bf16x2.f32 %0, %1, %2;" : "=r"(r) : "f"(hi), "f"(lo));
    return r;
}
__device__ __forceinline__ void mma_bf16(float* c, const uint32_t* a, const uint32_t* b) {
    asm volatile(
        "mma.sync.aligned.m16n8k16.row.col.f32.bf16.bf16.f32 "
        "{%0,%1,%2,%3}, {%4,%5,%6,%7}, {%8,%9}, {%0,%1,%2,%3};"
        : "+f"(c[0]), "+f"(c[1]), "+f"(c[2]), "+f"(c[3])
        : "r"(a[0]), "r"(a[1]), "r"(a[2]), "r"(a[3]), "r"(b[0]), "r"(b[1]));
}

// ---------------- kernel 1: mean over sequence ----------------
__global__ void k_mean(const float4* __restrict__ x4, float4* __restrict__ m4) {
    int b  = blockIdx.x >> 3;
    int d4 = ((blockIdx.x & 7) << 6) + threadIdx.x;     // 0..511
    const float4* p = x4 + (size_t)b * (S_ * D_ / 4) + d4;
    float4 acc[8];
    #pragma unroll
    for (int u = 0; u < 8; u++) acc[u] = make_float4(0.f, 0.f, 0.f, 0.f);
    for (int s = 0; s < S_; s += 8) {
        #pragma unroll
        for (int u = 0; u < 8; u++) {
            float4 v = __ldcs(&p[(size_t)(s + u) * (D_ / 4)]);
            acc[u].x += v.x; acc[u].y += v.y; acc[u].z += v.z; acc[u].w += v.w;
        }
    }
    #pragma unroll
    for (int u = 0; u < 4; u++) {
        acc[u].x += acc[u+4].x; acc[u].y += acc[u+4].y;
        acc[u].z += acc[u+4].z; acc[u].w += acc[u+4].w;
    }
    acc[0].x += acc[2].x; acc[0].y += acc[2].y; acc[0].z += acc[2].z; acc[0].w += acc[2].w;
    acc[1].x += acc[3].x; acc[1].y += acc[3].y; acc[1].z += acc[3].z; acc[1].w += acc[3].w;
    const float inv = 1.f / (float)S_;
    float4 m;
    m.x = (acc[0].x + acc[1].x) * inv;
    m.y = (acc[0].y + acc[1].y) * inv;
    m.z = (acc[0].z + acc[1].z) * inv;
    m.w = (acc[0].w + acc[1].w) * inv;
    m4[b * (D_ / 4) + d4] = m;
}

// ---------------- cp.async 3-stage GEMM (KT=64), 256 threads, warps 4x2 ----------------
// MODE 0: split-K x2 partial GEMM. grid = 2 * NFULL/NT blocks. out[split][128][NFULL] raw acc.
// MODE 3: full-K GEMM + fused softmax/einsum/sigmoid epilogue (NT must be 128 = one i-row).
template<int NT, int NFULL, int MODE>
__global__ void __launch_bounds__(256, 1)
k_gemm(const float* __restrict__ A, const float* __restrict__ Bm,
       const float* __restrict__ bias, float* __restrict__ out,
       const float* __restrict__ adj, const float* __restrict__ raw) {
    constexpr int ASZ = 128 * PADG;
    constexpr int BSZ = NT  * PADG;
    constexpr int NJ  = NT / 16;         // n8 tiles per warp (NT/2 cols / 8)
    constexpr int NA  = 8;               // 128 rows * 16 f4 / 256 thr
    constexpr int NB  = NT * 16 / 256;

    extern __shared__ __align__(16) float sm[];
    float* As = sm;                      // [STG][128][PADG]
    float* Bs = sm + STG * ASZ;          // [STG][NT ][PADG]

    const int tid  = threadIdx.x;
    const int warp = tid >> 5, lane = tid & 31;
    const int wy   = warp >> 1, wx = warp & 1;
    const int row0 = wy * 32;
    const int wxn0 = wx * (NT / 2);
    const int r    = lane >> 2, c = lane & 3;

    int n0, k0g, nkt;
    float* op = out;
    if (MODE == 0) {
        const int nblk = NFULL / NT;
        int split = blockIdx.x / nblk;
        n0  = (blockIdx.x % nblk) * NT;
        k0g = split * (D_ / 2);
        nkt = (D_ / 2) / KTILE;          // 16
        op  = out + (size_t)split * 128 * NFULL;
    } else {
        n0 = blockIdx.x * NT; k0g = 0; nkt = D_ / KTILE;   // 32
    }

    float acc[2][NJ][4];
    #pragma unroll
    for (int m = 0; m < 2; m++)
        #pragma unroll
        for (int j = 0; j < NJ; j++)
            acc[m][j][0] = acc[m][j][1] = acc[m][j][2] = acc[m][j][3] = 0.f;

    auto issue = [&](int kt) {
        const int st = kt % STG;
        const int k0 = k0g + kt * KTILE;
        #pragma unroll
        for (int u = 0; u < NA; u++) {
            int i = tid + u * 256, rr = i >> 4, c4 = i & 15;
            cp_async16(&As[st * ASZ + rr * PADG + c4 * 4], &A[(size_t)rr * D_ + k0 + c4 * 4]);
        }
        #pragma unroll
        for (int u = 0; u < NB; u++) {
            int i = tid + u * 256, rr = i >> 4, c4 = i & 15;
            cp_async16(&Bs[st * BSZ + rr * PADG + c4 * 4],
                       &Bm[(size_t)(n0 + rr) * D_ + k0 + c4 * 4]);
        }
    };

    issue(0); asm volatile("cp.async.commit_group;\n");
    issue(1); asm volatile("cp.async.commit_group;\n");

    for (int kt = 0; kt < nkt; kt++) {
        const int st = kt % STG;
        asm volatile("cp.async.wait_group 1;\n");
        __syncthreads();
        if (kt + 2 < nkt) issue(kt + 2);
        asm volatile("cp.async.commit_group;\n");

        const float* Ast = As + st * ASZ;
        const float* Bst = Bs + st * BSZ;
        #pragma unroll
        for (int h = 0; h < 4; h++) {
            const int kb = h * 16 + 2 * c;
            uint32_t a[2][4];
            #pragma unroll
            for (int m = 0; m < 2; m++) {
                const float* ap = Ast + (row0 + m * 16 + r) * PADG + kb;
                float2 v;
                v = *(const float2*)(ap);                 a[m][0] = f2bf2(v.x, v.y);
                v = *(const float2*)(ap + 8 * PADG);      a[m][1] = f2bf2(v.x, v.y);
                v = *(const float2*)(ap + 8);             a[m][2] = f2bf2(v.x, v.y);
                v = *(const float2*)(ap + 8 * PADG + 8);  a[m][3] = f2bf2(v.x, v.y);
            }
            #pragma unroll
            for (int j = 0; j < NJ; j++) {
                const float* bp = Bst + (wxn0 + j * 8 + r) * PADG + kb;
                float2 v;
                uint32_t b[2];
                v = *(const float2*)(bp);       b[0] = f2bf2(v.x, v.y);
                v = *(const float2*)(bp + 8);   b[1] = f2bf2(v.x, v.y);
                mma_bf16(acc[0][j], a[0], b);
                mma_bf16(acc[1][j], a[1], b);
            }
        }
    }

    if (MODE == 0) {
        // raw accumulator partials (bias added in reduce)
        #pragma unroll
        for (int m = 0; m < 2; m++)
            #pragma unroll
            for (int j = 0; j < NJ; j++) {
                int row = row0 + m * 16 + r;
                int col = n0 + wxn0 + j * 8 + 2 * c;
                *(float2*)&op[(size_t)row * NFULL + col] =
                    make_float2(acc[m][j][0], acc[m][j][1]);
                *(float2*)&op[(size_t)(row + 8) * NFULL + col] =
                    make_float2(acc[m][j][2], acc[m][j][3]);
            }
    } else {
        // fused: logits = adj[i,:] + 0.1*(acc + bw); softmax over j; dot raw; sigmoid
        asm volatile("cp.async.wait_group 0;\n");
        __syncthreads();
        float* logit = sm;                 // [128][130]
        float* rawS  = sm + 128 * 130;     // [128][129]
        const float* adjr = adj + (size_t)blockIdx.x * 128;
        #pragma unroll
        for (int m = 0; m < 2; m++)
            #pragma unroll
            for (int j = 0; j < NJ; j++) {
                int row  = row0 + m * 16 + r;
                int lcol = wxn0 + j * 8 + 2 * c;
                int gcol = n0 + lcol;
                float b0 = bias[gcol], b1 = bias[gcol + 1];
                float a0 = adjr[lcol], a1 = adjr[lcol + 1];
                *(float2*)&logit[row * 130 + lcol] =
                    make_float2(a0 + 0.1f * (acc[m][j][0] + b0),
                                a1 + 0.1f * (acc[m][j][1] + b1));
                *(float2*)&logit[(row + 8) * 130 + lcol] =
                    make_float2(a0 + 0.1f * (acc[m][j][2] + b0),
                                a1 + 0.1f * (acc[m][j][3] + b1));
            }
        // stage full raw table [b][j] with stride 129 (conflict-free row reads)
        #pragma unroll
        for (int u = 0; u < 16; u++) {
            int i4 = tid + u * 256;                         // 0..4095
            float4 v = ((const float4*)raw)[i4];
            int b = i4 >> 5, j4 = (i4 & 31) * 4;
            float* d = &rawS[b * 129 + j4];
            d[0] = v.x; d[1] = v.y; d[2] = v.z; d[3] = v.w;
        }
        __syncthreads();
        if (tid < 128) {
            const float* L = &logit[tid * 130];
            const float* R = &rawS[tid * 129];
            float mx = -1e30f;
            #pragma unroll 4
            for (int j = 0; j < 128; j++) mx = fmaxf(mx, L[j]);
            float sum = 0.f, dot = 0.f;
            #pragma unroll 4
            for (int j = 0; j < 128; j++) {
                float e = __expf(L[j] - mx);
                sum += e;
                dot += e * R[j];
            }
            float w = dot / sum;
            out[(size_t)tid * N_ + blockIdx.x] = 1.f / (1.f + __expf(-w));
        }
    }
}

// ---------------- ctx reduce: ctx = p0 + p1 + bc ----------------
__global__ void k_ctxred(const float4* __restrict__ p, const float4* __restrict__ bc4,
                         float4* __restrict__ ctx4) {
    #pragma unroll
    for (int u = 0; u < 2; u++) {
        int i = blockIdx.x * 512 + threadIdx.x + u * 256;   // 0..65535 f4
        float4 a = p[i], b = p[65536 + i], c = bc4[i & 511];
        float4 o;
        o.x = a.x + b.x + c.x; o.y = a.y + b.y + c.y;
        o.z = a.z + b.z + c.z; o.w = a.w + b.w + c.w;
        ctx4[i] = o;
    }
}

// ---------------- raw-score split-K partials (fp32, deterministic) ----------------
__global__ void k_rawpart(const float* __restrict__ ctx, const float* __restrict__ rs,
                          float* __restrict__ part) {
    __shared__ float cs [128][20];
    __shared__ float rss[128][20];
    const int tid = threadIdx.x;
    const int k0  = blockIdx.x * 16;
    #pragma unroll
    for (int u = 0; u < 2; u++) {
        int i  = tid + u * 256;
        int rr = i >> 2, cc = (i & 3) * 4;
        *(float4*)&cs [rr][cc] = *(const float4*)&ctx[(size_t)rr * D_ + k0 + cc];
        *(float4*)&rss[rr][cc] = *(const float4*)&rs [(size_t)rr * D_ + k0 + cc];
    }
    __syncthreads();
    const int bb = tid >> 4;
    const int jj = tid & 15;
    float a[8][8];
    #pragma unroll
    for (int u = 0; u < 8; u++)
        #pragma unroll
        for (int v = 0; v < 8; v++) a[u][v] = 0.f;
    #pragma unroll
    for (int k = 0; k < 16; k++) {
        float cv[8], rv[8];
        #pragma unroll
        for (int u = 0; u < 8; u++) { cv[u] = cs[bb + 16*u][k]; rv[u] = rss[jj + 16*u][k]; }
        #pragma unroll
        for (int u = 0; u < 8; u++)
            #pragma unroll
            for (int v = 0; v < 8; v++) a[u][v] += cv[u] * rv[v];
    }
    float* po = part + (size_t)blockIdx.x * NN_;
    #pragma unroll
    for (int u = 0; u < 8; u++)
        #pragma unroll
        for (int v = 0; v < 8; v++)
            po[(bb + 16*u) * N_ + (jj + 16*v)] = a[u][v];
}

// ---------------- raw reduce over 128 partials ----------------
__global__ void k_rawred(const float* __restrict__ part, float* __restrict__ raw) {
    int i = blockIdx.x * 256 + threadIdx.x;   // 0..16383
    float s = 0.f;
    #pragma unroll 8
    for (int ks = 0; ks < 128; ks++) s += part[(size_t)ks * NN_ + i];
    raw[i] = s;
}

// ---------------- launch ----------------
extern "C" void kernel_launch(void* const* d_in, const int* in_sizes, int n_in,
                              void* d_out, int out_size) {
    const float* x   = (const float*)d_in[0];
    const float* rs  = (const float*)d_in[1];
    const float* Wc  = (const float*)d_in[2];
    const float* bc  = (const float*)d_in[3];
    const float* Ww  = (const float*)d_in[4];
    const float* bw  = (const float*)d_in[5];
    const float* adj = (const float*)d_in[6];
    float* out = (float*)d_out;

    float *p_mean, *p_ctx, *p_ctxp, *p_part, *p_raw;
    cudaGetSymbolAddress((void**)&p_mean, g_mean);
    cudaGetSymbolAddress((void**)&p_ctx,  g_ctx);
    cudaGetSymbolAddress((void**)&p_ctxp, g_ctxp);
    cudaGetSymbolAddress((void**)&p_part, g_part);
    cudaGetSymbolAddress((void**)&p_raw,  g_raw);

    // 1. mean over S (HBM-bound, 512 MB)
    k_mean<<<B_ * 8, 64>>>((const float4*)x, (float4*)p_mean);

    // 2. context partials: split-K x2, 128 blocks
    {
        size_t sh = (size_t)STG * (128 + 32) * PADG * sizeof(float);
        cudaFuncSetAttribute((const void*)k_gemm<32, D_, 0>,
                             cudaFuncAttributeMaxDynamicSharedMemorySize, (int)sh);
        k_gemm<32, D_, 0><<<128, 256, sh>>>(p_mean, Wc, nullptr, p_ctxp, nullptr, nullptr);
    }
    // 2b. ctx = p0 + p1 + bc
    k_ctxred<<<128, 256>>>((const float4*)p_ctxp, (const float4*)bc, (float4*)p_ctx);

    // 3. raw = ctx @ rs^T (split-K partials + reduce)
    k_rawpart<<<128, 256>>>(p_ctx, rs, p_part);
    k_rawred<<<64, 256>>>(p_part, p_raw);

    // 4+5. warp GEMM + fused softmax/einsum/sigmoid
    {
        size_t sh = (size_t)STG * (128 + 128) * PADG * sizeof(float);
        cudaFuncSetAttribute((const void*)k_gemm<128, NN_, 3>,
                             cudaFuncAttributeMaxDynamicSharedMemorySize, (int)sh);
        k_gemm<128, NN_, 3><<<128, 256, sh>>>(p_ctx, Ww, bw, out, adj, p_raw);
    }
}